// round 16
// baseline (speedup 1.0000x reference)
#include <cuda_runtime.h>
#include <cuda_fp16.h>
#include <cstdint>

// ---------------- problem constants ----------------
#define NUM_USERS   100000
#define NUM_ITEMS   50000
#define DUMMYIDX    150000
#define BATCH       4096
#define NPOSW       16384
#define NNEGW       32768
#define WLEN        11
#define NWIN        7
#define CTXW        5
#define POS_ROWS    (NPOSW * NWIN)
#define NEG_ROWS    (NNEGW * NWIN)
#define POS_ELEMS   (POS_ROWS * CTXW)   // 573440
#define NEG_ELEMS   (NEG_ROWS * CTXW)   // 1146880
#define POS_LOGITS  (POS_ROWS * 4)
#define NEG_LOGITS  (NEG_ROWS * 4)
#define EMB_ROWS    (DUMMYIDX + 1)      // 150001
#define EMB_VEC4    (EMB_ROWS * 32)     // uint2-packed half4 count = 4,800,032

// ---------------- scratch ----------------
__device__ int          g_pos[NPOSW * WLEN];
__device__ int          g_neg[NNEGW * WLEN];
__device__ float        g_acc[2];
__device__ unsigned int g_done;
__device__ uint2        g_emb16[EMB_VEC4];   // fp16 emb: 38.4MB, row = 32 uint2

struct Keys10  { uint32_t k[10][2]; };
struct KeysR10 { uint32_t kh[10][2]; uint32_t kl[10][2]; };

// ---------------- threefry-2x32, 20 rounds [VERIFIED] ----------------
__host__ __device__ __forceinline__ void tf2x32(uint32_t k0, uint32_t k1,
                                                uint32_t x0, uint32_t x1,
                                                uint32_t& o0, uint32_t& o1) {
    uint32_t ks2 = k0 ^ k1 ^ 0x1BD11BDAu;
    x0 += k0; x1 += k1;
#define TFR(r) { x0 += x1; x1 = (x1 << (r)) | (x1 >> (32 - (r))); x1 ^= x0; }
    TFR(13) TFR(15) TFR(26) TFR(6)
    x0 += k1;  x1 += ks2 + 1u;
    TFR(17) TFR(29) TFR(16) TFR(24)
    x0 += ks2; x1 += k0 + 2u;
    TFR(13) TFR(15) TFR(26) TFR(6)
    x0 += k0;  x1 += k1 + 3u;
    TFR(17) TFR(29) TFR(16) TFR(24)
    x0 += k1;  x1 += ks2 + 4u;
    TFR(13) TFR(15) TFR(26) TFR(6)
    x0 += ks2; x1 += k0 + 5u;
#undef TFR
    o0 = x0; o1 = x1;
}

__device__ __forceinline__ uint32_t rbits_modern(uint32_t k0, uint32_t k1, uint32_t i) {
    uint32_t a, b;
    tf2x32(k0, k1, 0u, i, a, b);
    return a ^ b;
}

// ---------------- kernels ----------------
// fp32 -> fp16 staging of emb (runs concurrently with walk kernels)
__global__ void __launch_bounds__(256) convert_kernel(const float4* __restrict__ emb4)
{
    int i = blockIdx.x * blockDim.x + threadIdx.x;
    if (i >= EMB_VEC4) return;
    float4 v = emb4[i];
    __half2 h01 = __floats2half2_rn(v.x, v.y);
    __half2 h23 = __floats2half2_rn(v.z, v.w);
    uint2 o;
    o.x = *reinterpret_cast<uint32_t*>(&h01);
    o.y = *reinterpret_cast<uint32_t*>(&h23);
    g_emb16[i] = o;
}

__global__ void __launch_bounds__(256) pos_walk_kernel(
    Keys10 keys, const int* __restrict__ batch,
    const int* __restrict__ rowptr_ui, const int* __restrict__ col_ui,
    const int* __restrict__ rowcount_ui, int nnz_ui,
    const int* __restrict__ rowptr_iu, const int* __restrict__ col_iu,
    const int* __restrict__ rowcount_iu, int nnz_iu)
{
    int t = blockIdx.x * blockDim.x + threadIdx.x;
    if (t == 0) { g_acc[0] = 0.0f; g_acc[1] = 0.0f; g_done = 0u; }
    if (t >= NPOSW) return;
    int cur = batch[t & (BATCH - 1)];
    g_pos[t * WLEN + 0] = cur + NUM_ITEMS;

    #pragma unroll
    for (int i = 0; i < 10; i++) {
        uint32_t bits = rbits_modern(keys.k[i][0], keys.k[i][1], (uint32_t)t);
        float r = __uint_as_float((bits >> 9) | 0x3f800000u) - 1.0f;

        const int *rowptr, *col, *rowcount;
        int nnz, nrows;
        if ((i & 1) == 0) { rowptr = rowptr_ui; col = col_ui; rowcount = rowcount_ui; nnz = nnz_ui; nrows = NUM_USERS; }
        else              { rowptr = rowptr_iu; col = col_iu; rowcount = rowcount_iu; nnz = nnz_iu; nrows = NUM_ITEMS; }

        bool mask = (cur >= DUMMYIDX);
        int s = cur; if (s < 0) s = 0; if (s > nrows - 1) s = nrows - 1;
        int count = rowcount[s];
        int idx = (int)(r * (float)count) + rowptr[s];
        if (idx > nnz - 1) idx = nnz - 1;
        int nxt = col[idx];
        if (mask || count == 0) nxt = DUMMYIDX;
        cur = nxt;

        int off = ((i + 1) & 1) ? 0 : NUM_ITEMS;
        int adj = cur + off;
        if (adj > DUMMYIDX) adj = DUMMYIDX;
        g_pos[t * WLEN + i + 1] = adj;
    }
}

// neg: split-key randint [VERIFIED]
__global__ void __launch_bounds__(256) neg_walk_kernel(KeysR10 keys, const int* __restrict__ batch)
{
    int t = blockIdx.x * blockDim.x + threadIdx.x;
    if (t >= NNEGW) return;
    int cur = batch[t & (BATCH - 1)];
    g_neg[t * WLEN + 0] = cur + NUM_ITEMS;

    #pragma unroll
    for (int i = 0; i < 10; i++) {
        uint32_t span = ((i & 1) == 0) ? (uint32_t)NUM_ITEMS : (uint32_t)NUM_USERS;
        uint32_t hi = rbits_modern(keys.kh[i][0], keys.kh[i][1], (uint32_t)t);
        uint32_t lo = rbits_modern(keys.kl[i][0], keys.kl[i][1], (uint32_t)t);
        uint32_t m = 65536u % span;
        m = (m * m) % span;
        uint32_t ro = ((hi % span) * m + (lo % span)) % span;
        cur = (int)ro;
        int off = ((i + 1) & 1) ? 0 : NUM_ITEMS;
        g_neg[t * WLEN + i + 1] = cur + off;
    }
}

__global__ void __launch_bounds__(256) emit_kernel(float* __restrict__ out)
{
    int e = blockIdx.x * blockDim.x + threadIdx.x;
    if (e >= POS_ELEMS + NEG_ELEMS) return;
    int val;
    if (e < POS_ELEMS) {
        int w = e / CTXW, c = e % CTXW;
        int j = w / NPOSW, t = w % NPOSW;
        val = g_pos[t * WLEN + j + c];
    } else {
        int e2 = e - POS_ELEMS;
        int w = e2 / CTXW, c = e2 % CTXW;
        int j = w / NNEGW, t = w % NNEGW;
        val = g_neg[t * WLEN + j + c];
    }
    out[1 + e] = (float)val;
}

// packed f32x2 partial dot (per-lane 4 floats in two ull)
__device__ __forceinline__ float dot128_partial(unsigned long long alo, unsigned long long ahi,
                                                unsigned long long blo, unsigned long long bhi)
{
    unsigned long long acc;
    asm("mul.rn.f32x2 %0, %1, %2;" : "=l"(acc) : "l"(alo), "l"(blo));
    asm("fma.rn.f32x2 %0, %1, %2, %3;" : "=l"(acc) : "l"(ahi), "l"(bhi), "l"(acc));
    uint32_t lo, hi;
    asm("mov.b64 {%0,%1}, %2;" : "=r"(lo), "=r"(hi) : "l"(acc));
    return __uint_as_float(lo) + __uint_as_float(hi);
}

__device__ __forceinline__ unsigned long long pack2(float a, float b) {
    unsigned long long r;
    asm("mov.b64 %0, {%1,%2};" : "=l"(r) : "r"(__float_as_uint(a)), "r"(__float_as_uint(b)));
    return r;
}

// load one fp16 row slice (4 dims for this lane) and expand to fp32 pair-of-ull
__device__ __forceinline__ void load_row16(int nj, int lane,
                                           unsigned long long& lo, unsigned long long& hi)
{
    uint2 q = g_emb16[nj * 32 + lane];
    __half2 h01 = *reinterpret_cast<__half2*>(&q.x);
    __half2 h23 = *reinterpret_cast<__half2*>(&q.y);
    float2 f01 = __half22float2(h01);
    float2 f23 = __half22float2(h23);
    lo = pack2(f01.x, f01.y);
    hi = pack2(f23.x, f23.y);
}

// one warp per walk; fp16 row loads; pipelined; butterfly reductions; finalize folded
__global__ void __launch_bounds__(256, 5) loss_kernel(float* __restrict__ out)
{
    int warp = (blockIdx.x * blockDim.x + threadIdx.x) >> 5;
    int lane = threadIdx.x & 31;
    bool is_pos;
    const int* walks;
    int w;
    if (warp < NPOSW) { is_pos = true;  walks = g_pos; w = warp; }
    else              { is_pos = false; walks = g_neg; w = warp - NPOSW; }

    int myn = (lane < WLEN) ? walks[w * WLEN + lane] : 0;

    unsigned long long vlo[WLEN], vhi[WLEN];
    #pragma unroll
    for (int j = 0; j < 5; j++) {
        int nj = __shfl_sync(0xffffffffu, myn, j);
        load_row16(nj, lane, vlo[j], vhi[j]);
    }

    float myp = 0.0f;
    #pragma unroll
    for (int b = 1; b <= 10; b++) {
        if (b + 4 <= 10) {   // prefetch row b+4
            int nj = __shfl_sync(0xffffffffu, myn, b + 4);
            load_row16(nj, lane, vlo[b + 4], vhi[b + 4]);
        }
        #pragma unroll
        for (int a = (b - 4 > 0 ? b - 4 : 0); a < b; a++) {
            if (a <= 6) {
                float p = dot128_partial(vlo[a], vhi[a], vlo[b], vhi[b]);
                #pragma unroll
                for (int o = 16; o > 0; o >>= 1) p += __shfl_xor_sync(0xffffffffu, p, o);
                int k = a * 4 + (b - a - 1);          // logit index 0..27
                if (lane == k) myp = p;
            }
        }
    }

    // one transcendental chain per warp (same per-term formula)
    float s = __fdividef(1.0f, 1.0f + __expf(-myp));
    float x = is_pos ? s : (1.0f - s);
    float term = -__logf(x + 1e-15f);
    if (lane >= 28) term = 0.0f;
    #pragma unroll
    for (int o = 16; o > 0; o >>= 1) term += __shfl_xor_sync(0xffffffffu, term, o);

    __shared__ float sh[8];
    if (lane == 0) sh[threadIdx.x >> 5] = term;
    __syncthreads();
    if (threadIdx.x == 0) {
        float bs = 0.0f;
        #pragma unroll
        for (int i = 0; i < 8; i++) bs += sh[i];
        atomicAdd(&g_acc[is_pos ? 0 : 1], bs);
        __threadfence();
        unsigned int prev = atomicAdd(&g_done, 1u);
        if (prev == gridDim.x - 1u) {
            g_done = 0u;
            out[0] = g_acc[0] * (1.0f / (float)POS_LOGITS)
                   + g_acc[1] * (1.0f / (float)NEG_LOGITS);
        }
    }
}

// ---------------- launch ----------------
static void foldlike_split(uint32_t k0, uint32_t k1,
                           uint32_t& nk0, uint32_t& nk1,
                           uint32_t& sk0, uint32_t& sk1)
{
    tf2x32(k0, k1, 0u, 0u, nk0, nk1);
    tf2x32(k0, k1, 0u, 1u, sk0, sk1);
}

extern "C" void kernel_launch(void* const* d_in, const int* in_sizes, int n_in,
                              void* d_out, int out_size)
{
    const float* emb        = (const float*)d_in[0];
    const int* rowptr_ui    = (const int*)d_in[1];
    const int* col_ui       = (const int*)d_in[2];
    const int* rowcount_ui  = (const int*)d_in[3];
    const int* rowptr_iu    = (const int*)d_in[4];
    const int* col_iu       = (const int*)d_in[5];
    const int* rowcount_iu  = (const int*)d_in[6];
    const int* batch        = (const int*)d_in[7];
    int nnz_ui = in_sizes[2];
    int nnz_iu = in_sizes[5];
    float* out = (float*)d_out;

    uint32_t kp0, kp1, kn0, kn1;
    foldlike_split(0u, 42u, kp0, kp1, kn0, kn1);

    Keys10 pk;
    KeysR10 nkr;
    uint32_t c0 = kp0, c1 = kp1;
    for (int i = 0; i < 10; i++) {
        uint32_t n0, n1, s0, s1;
        foldlike_split(c0, c1, n0, n1, s0, s1);
        pk.k[i][0] = s0; pk.k[i][1] = s1;
        c0 = n0; c1 = n1;
    }
    c0 = kn0; c1 = kn1;
    for (int i = 0; i < 10; i++) {
        uint32_t n0, n1, s0, s1;
        foldlike_split(c0, c1, n0, n1, s0, s1);
        uint32_t h0, h1, l0, l1;
        foldlike_split(s0, s1, h0, h1, l0, l1);   // randint internal split(sk)
        nkr.kh[i][0] = h0; nkr.kh[i][1] = h1;
        nkr.kl[i][0] = l0; nkr.kl[i][1] = l1;
        c0 = n0; c1 = n1;
    }

    static cudaStream_t s2 = nullptr;
    static cudaEvent_t eF = nullptr, eC = nullptr, eN = nullptr, eJ = nullptr;
    if (!s2) {
        cudaStreamCreateWithFlags(&s2, cudaStreamNonBlocking);
        cudaEventCreateWithFlags(&eF, cudaEventDisableTiming);
        cudaEventCreateWithFlags(&eC, cudaEventDisableTiming);
        cudaEventCreateWithFlags(&eN, cudaEventDisableTiming);
        cudaEventCreateWithFlags(&eJ, cudaEventDisableTiming);
    }

    // DAG: s0: pos -> neg -> (wait convert) loss(+finalize)
    //      s2: convert -> (wait walks) emit
    cudaEventRecord(eF, 0);
    cudaStreamWaitEvent(s2, eF, 0);

    convert_kernel<<<(EMB_VEC4 + 255) / 256, 256, 0, s2>>>((const float4*)emb);
    cudaEventRecord(eC, s2);

    pos_walk_kernel<<<NPOSW / 256, 256, 0, 0>>>(pk, batch,
        rowptr_ui, col_ui, rowcount_ui, nnz_ui, rowptr_iu, col_iu, rowcount_iu, nnz_iu);
    neg_walk_kernel<<<NNEGW / 256, 256, 0, 0>>>(nkr, batch);
    cudaEventRecord(eN, 0);

    cudaStreamWaitEvent(s2, eN, 0);
    emit_kernel<<<(POS_ELEMS + NEG_ELEMS + 255) / 256, 256, 0, s2>>>(out);
    cudaEventRecord(eJ, s2);

    cudaStreamWaitEvent(0, eC, 0);
    loss_kernel<<<(NPOSW + NNEGW) / 8, 256, 0, 0>>>(out);
    cudaStreamWaitEvent(0, eJ, 0);
}

// round 17
// speedup vs baseline: 1.5834x; 1.5834x over previous
#include <cuda_runtime.h>
#include <cstdint>

// ---------------- problem constants ----------------
#define NUM_USERS   100000
#define NUM_ITEMS   50000
#define DUMMYIDX    150000
#define BATCH       4096
#define NPOSW       16384
#define NNEGW       32768
#define WLEN        11
#define NWIN        7
#define CTXW        5
#define POS_ROWS    (NPOSW * NWIN)
#define NEG_ROWS    (NNEGW * NWIN)
#define POS_ELEMS   (POS_ROWS * CTXW)   // 573440
#define NEG_ELEMS   (NEG_ROWS * CTXW)   // 1146880
#define POS_LOGITS  (POS_ROWS * 4)
#define NEG_LOGITS  (NEG_ROWS * 4)

// ---------------- scratch ----------------
__device__ int          g_pos[NPOSW * WLEN];
__device__ int          g_neg[NNEGW * WLEN];
__device__ float        g_acc[2];
__device__ unsigned int g_done;

struct Keys10  { uint32_t k[10][2]; };
struct KeysR10 { uint32_t kh[10][2]; uint32_t kl[10][2]; };

// ---------------- threefry-2x32, 20 rounds [VERIFIED] ----------------
__host__ __device__ __forceinline__ void tf2x32(uint32_t k0, uint32_t k1,
                                                uint32_t x0, uint32_t x1,
                                                uint32_t& o0, uint32_t& o1) {
    uint32_t ks2 = k0 ^ k1 ^ 0x1BD11BDAu;
    x0 += k0; x1 += k1;
#define TFR(r) { x0 += x1; x1 = (x1 << (r)) | (x1 >> (32 - (r))); x1 ^= x0; }
    TFR(13) TFR(15) TFR(26) TFR(6)
    x0 += k1;  x1 += ks2 + 1u;
    TFR(17) TFR(29) TFR(16) TFR(24)
    x0 += ks2; x1 += k0 + 2u;
    TFR(13) TFR(15) TFR(26) TFR(6)
    x0 += k0;  x1 += k1 + 3u;
    TFR(17) TFR(29) TFR(16) TFR(24)
    x0 += k1;  x1 += ks2 + 4u;
    TFR(13) TFR(15) TFR(26) TFR(6)
    x0 += ks2; x1 += k0 + 5u;
#undef TFR
    o0 = x0; o1 = x1;
}

__device__ __forceinline__ uint32_t rbits_modern(uint32_t k0, uint32_t k1, uint32_t i) {
    uint32_t a, b;
    tf2x32(k0, k1, 0u, i, a, b);
    return a ^ b;
}

// ---------------- kernels ----------------
__global__ void __launch_bounds__(256) pos_walk_kernel(
    Keys10 keys, const int* __restrict__ batch,
    const int* __restrict__ rowptr_ui, const int* __restrict__ col_ui,
    const int* __restrict__ rowcount_ui, int nnz_ui,
    const int* __restrict__ rowptr_iu, const int* __restrict__ col_iu,
    const int* __restrict__ rowcount_iu, int nnz_iu)
{
    int t = blockIdx.x * blockDim.x + threadIdx.x;
    if (t == 0) { g_acc[0] = 0.0f; g_acc[1] = 0.0f; g_done = 0u; }
    if (t >= NPOSW) return;
    int cur = batch[t & (BATCH - 1)];
    g_pos[t * WLEN + 0] = cur + NUM_ITEMS;

    #pragma unroll
    for (int i = 0; i < 10; i++) {
        uint32_t bits = rbits_modern(keys.k[i][0], keys.k[i][1], (uint32_t)t);
        float r = __uint_as_float((bits >> 9) | 0x3f800000u) - 1.0f;

        const int *rowptr, *col, *rowcount;
        int nnz, nrows;
        if ((i & 1) == 0) { rowptr = rowptr_ui; col = col_ui; rowcount = rowcount_ui; nnz = nnz_ui; nrows = NUM_USERS; }
        else              { rowptr = rowptr_iu; col = col_iu; rowcount = rowcount_iu; nnz = nnz_iu; nrows = NUM_ITEMS; }

        bool mask = (cur >= DUMMYIDX);
        int s = cur; if (s < 0) s = 0; if (s > nrows - 1) s = nrows - 1;
        int count = rowcount[s];
        int idx = (int)(r * (float)count) + rowptr[s];
        if (idx > nnz - 1) idx = nnz - 1;
        int nxt = col[idx];
        if (mask || count == 0) nxt = DUMMYIDX;
        cur = nxt;

        int off = ((i + 1) & 1) ? 0 : NUM_ITEMS;
        int adj = cur + off;
        if (adj > DUMMYIDX) adj = DUMMYIDX;
        g_pos[t * WLEN + i + 1] = adj;
    }
}

// neg: split-key randint [VERIFIED]
__global__ void __launch_bounds__(256) neg_walk_kernel(KeysR10 keys, const int* __restrict__ batch)
{
    int t = blockIdx.x * blockDim.x + threadIdx.x;
    if (t >= NNEGW) return;
    int cur = batch[t & (BATCH - 1)];
    g_neg[t * WLEN + 0] = cur + NUM_ITEMS;

    #pragma unroll
    for (int i = 0; i < 10; i++) {
        uint32_t span = ((i & 1) == 0) ? (uint32_t)NUM_ITEMS : (uint32_t)NUM_USERS;
        uint32_t hi = rbits_modern(keys.kh[i][0], keys.kh[i][1], (uint32_t)t);
        uint32_t lo = rbits_modern(keys.kl[i][0], keys.kl[i][1], (uint32_t)t);
        uint32_t m = 65536u % span;
        m = (m * m) % span;
        uint32_t ro = ((hi % span) * m + (lo % span)) % span;
        cur = (int)ro;
        int off = ((i + 1) & 1) ? 0 : NUM_ITEMS;
        g_neg[t * WLEN + i + 1] = cur + off;
    }
}

__global__ void __launch_bounds__(256) emit_kernel(float* __restrict__ out)
{
    int e = blockIdx.x * blockDim.x + threadIdx.x;
    if (e >= POS_ELEMS + NEG_ELEMS) return;
    int val;
    if (e < POS_ELEMS) {
        int w = e / CTXW, c = e % CTXW;
        int j = w / NPOSW, t = w % NPOSW;
        val = g_pos[t * WLEN + j + c];
    } else {
        int e2 = e - POS_ELEMS;
        int w = e2 / CTXW, c = e2 % CTXW;
        int j = w / NNEGW, t = w % NNEGW;
        val = g_neg[t * WLEN + j + c];
    }
    out[1 + e] = (float)val;
}

// packed f32x2 partial dot over one ull-pair (4 floats per operand half)
__device__ __forceinline__ float dot128_partial(unsigned long long alo, unsigned long long ahi,
                                                unsigned long long blo, unsigned long long bhi)
{
    unsigned long long acc;
    asm("mul.rn.f32x2 %0, %1, %2;" : "=l"(acc) : "l"(alo), "l"(blo));
    asm("fma.rn.f32x2 %0, %1, %2, %3;" : "=l"(acc) : "l"(ahi), "l"(bhi), "l"(acc));
    uint32_t lo, hi;
    asm("mov.b64 {%0,%1}, %2;" : "=r"(lo), "=r"(hi) : "l"(acc));
    return __uint_as_float(lo) + __uint_as_float(hi);
}

// TWO walks per warp (16 lanes each, 8 dims/lane); 4-stage reductions serve both
__global__ void __launch_bounds__(256, 3) loss_kernel(const float* __restrict__ emb,
                                                      float* __restrict__ out)
{
    int gw   = (blockIdx.x * blockDim.x + threadIdx.x) >> 5;   // global warp
    int lane = threadIdx.x & 31;
    int hl   = lane & 15;                                      // lane within half
    int w    = 2 * gw + (lane >> 4);                           // this half's walk
    bool is_pos = (w < NPOSW);                                 // uniform per block (16 walks/block)
    const int* walks = is_pos ? g_pos : g_neg;
    int wl = is_pos ? w : w - NPOSW;

    int myn = (hl < WLEN) ? walks[wl * WLEN + hl] : 0;

    unsigned long long v0[WLEN], v1[WLEN], v2[WLEN], v3[WLEN];
    #pragma unroll
    for (int j = 0; j < 5; j++) {
        int nj = __shfl_sync(0xffffffffu, myn, (lane & 16) | j);
        const float* base = emb + (size_t)nj * 128 + hl * 8;
        ulonglong2 qa = *reinterpret_cast<const ulonglong2*>(base);
        ulonglong2 qb = *reinterpret_cast<const ulonglong2*>(base + 4);
        v0[j] = qa.x; v1[j] = qa.y; v2[j] = qb.x; v3[j] = qb.y;
    }

    float myp_a = 0.0f, myp_b = 0.0f;
    #pragma unroll
    for (int b = 1; b <= 10; b++) {
        if (b + 4 <= 10) {   // prefetch row b+4
            int nj = __shfl_sync(0xffffffffu, myn, (lane & 16) | (b + 4));
            const float* base = emb + (size_t)nj * 128 + hl * 8;
            ulonglong2 qa = *reinterpret_cast<const ulonglong2*>(base);
            ulonglong2 qb = *reinterpret_cast<const ulonglong2*>(base + 4);
            v0[b + 4] = qa.x; v1[b + 4] = qa.y; v2[b + 4] = qb.x; v3[b + 4] = qb.y;
        }
        #pragma unroll
        for (int a = (b - 4 > 0 ? b - 4 : 0); a < b; a++) {
            if (a <= 6) {
                float p = dot128_partial(v0[a], v1[a], v0[b], v1[b])
                        + dot128_partial(v2[a], v3[a], v2[b], v3[b]);
                #pragma unroll
                for (int o = 8; o > 0; o >>= 1) p += __shfl_xor_sync(0xffffffffu, p, o);
                int k = a * 4 + (b - a - 1);          // logit index 0..27
                if (k < 16) { if (hl == k)      myp_a = p; }
                else        { if (hl == k - 16) myp_b = p; }
            }
        }
    }

    // two transcendental passes per warp (logits 0-15 and 16-27), same per-term formula
    float sA = __fdividef(1.0f, 1.0f + __expf(-myp_a));
    float xA = is_pos ? sA : (1.0f - sA);
    float tA = -__logf(xA + 1e-15f);
    float sB = __fdividef(1.0f, 1.0f + __expf(-myp_b));
    float xB = is_pos ? sB : (1.0f - sB);
    float tB = -__logf(xB + 1e-15f);
    float term = tA + ((hl < 12) ? tB : 0.0f);
    #pragma unroll
    for (int o = 8; o > 0; o >>= 1) term += __shfl_xor_sync(0xffffffffu, term, o);

    __shared__ float sh[16];
    if (hl == 0) sh[((threadIdx.x >> 5) << 1) | (lane >> 4)] = term;
    __syncthreads();
    if (threadIdx.x == 0) {
        float bs = 0.0f;
        #pragma unroll
        for (int i = 0; i < 16; i++) bs += sh[i];
        atomicAdd(&g_acc[is_pos ? 0 : 1], bs);
        __threadfence();
        unsigned int prev = atomicAdd(&g_done, 1u);
        if (prev == gridDim.x - 1u) {
            g_done = 0u;
            out[0] = g_acc[0] * (1.0f / (float)POS_LOGITS)
                   + g_acc[1] * (1.0f / (float)NEG_LOGITS);
        }
    }
}

// ---------------- launch ----------------
static void foldlike_split(uint32_t k0, uint32_t k1,
                           uint32_t& nk0, uint32_t& nk1,
                           uint32_t& sk0, uint32_t& sk1)
{
    tf2x32(k0, k1, 0u, 0u, nk0, nk1);
    tf2x32(k0, k1, 0u, 1u, sk0, sk1);
}

extern "C" void kernel_launch(void* const* d_in, const int* in_sizes, int n_in,
                              void* d_out, int out_size)
{
    const float* emb        = (const float*)d_in[0];
    const int* rowptr_ui    = (const int*)d_in[1];
    const int* col_ui       = (const int*)d_in[2];
    const int* rowcount_ui  = (const int*)d_in[3];
    const int* rowptr_iu    = (const int*)d_in[4];
    const int* col_iu       = (const int*)d_in[5];
    const int* rowcount_iu  = (const int*)d_in[6];
    const int* batch        = (const int*)d_in[7];
    int nnz_ui = in_sizes[2];
    int nnz_iu = in_sizes[5];
    float* out = (float*)d_out;

    uint32_t kp0, kp1, kn0, kn1;
    foldlike_split(0u, 42u, kp0, kp1, kn0, kn1);

    Keys10 pk;
    KeysR10 nkr;
    uint32_t c0 = kp0, c1 = kp1;
    for (int i = 0; i < 10; i++) {
        uint32_t n0, n1, s0, s1;
        foldlike_split(c0, c1, n0, n1, s0, s1);
        pk.k[i][0] = s0; pk.k[i][1] = s1;
        c0 = n0; c1 = n1;
    }
    c0 = kn0; c1 = kn1;
    for (int i = 0; i < 10; i++) {
        uint32_t n0, n1, s0, s1;
        foldlike_split(c0, c1, n0, n1, s0, s1);
        uint32_t h0, h1, l0, l1;
        foldlike_split(s0, s1, h0, h1, l0, l1);   // randint internal split(sk)
        nkr.kh[i][0] = h0; nkr.kh[i][1] = h1;
        nkr.kl[i][0] = l0; nkr.kl[i][1] = l1;
        c0 = n0; c1 = n1;
    }

    static cudaStream_t s2 = nullptr;
    static cudaEvent_t eF = nullptr, eP = nullptr, eN = nullptr, eJ = nullptr;
    if (!s2) {
        cudaStreamCreateWithFlags(&s2, cudaStreamNonBlocking);
        cudaEventCreateWithFlags(&eF, cudaEventDisableTiming);
        cudaEventCreateWithFlags(&eP, cudaEventDisableTiming);
        cudaEventCreateWithFlags(&eN, cudaEventDisableTiming);
        cudaEventCreateWithFlags(&eJ, cudaEventDisableTiming);
    }

    // DAG: pos(s0) ∥ neg(s2); emit(s2) after both; loss(s0, incl. finalize) after both
    cudaEventRecord(eF, 0);
    cudaStreamWaitEvent(s2, eF, 0);

    pos_walk_kernel<<<NPOSW / 256, 256, 0, 0>>>(pk, batch,
        rowptr_ui, col_ui, rowcount_ui, nnz_ui, rowptr_iu, col_iu, rowcount_iu, nnz_iu);
    cudaEventRecord(eP, 0);

    neg_walk_kernel<<<NNEGW / 256, 256, 0, s2>>>(nkr, batch);
    cudaEventRecord(eN, s2);

    cudaStreamWaitEvent(s2, eP, 0);
    emit_kernel<<<(POS_ELEMS + NEG_ELEMS + 255) / 256, 256, 0, s2>>>(out);
    cudaEventRecord(eJ, s2);

    cudaStreamWaitEvent(0, eN, 0);
    loss_kernel<<<(NPOSW + NNEGW) / 16, 256, 0, 0>>>(emb, out);
    cudaStreamWaitEvent(0, eJ, 0);
}